// round 1
// baseline (speedup 1.0000x reference)
#include <cuda_runtime.h>
#include <math.h>

#define BSZ   32
#define SEQ   2048
#define DIM   512
#define DGLU  1024
#define MROWS (BSZ * SEQ)   // 65536

// ---------------- scratch (device globals; no allocation allowed) ----------
__device__ float g_bufA[(size_t)MROWS * DIM];
__device__ float g_bufB[(size_t)MROWS * DIM];
__device__ float g_bufC[(size_t)MROWS * DIM];
__device__ float g_bufD[(size_t)MROWS * DIM];
__device__ float g_bufE[(size_t)MROWS * DGLU];
__device__ float g_bufF[(size_t)MROWS * DGLU];

__device__ __forceinline__ float sigmoidf_(float v) { return 1.f / (1.f + expf(-v)); }

enum { MODE_PLAIN = 0, MODE_SIG = 1, MODE_LAM = 2, MODE_U = 3, MODE_GLU = 4 };

// ---------------- 128x128x8 fp32 GEMM with fused epilogue -------------------
// C[M,N] = epilogue(A[M,K] @ W[K,N] + bias[N])
template <int MODE>
__global__ __launch_bounds__(256, 2)
void sgemm_ep(const float* __restrict__ A, const float* __restrict__ W,
              const float* __restrict__ bias, float* __restrict__ C,
              const float* __restrict__ aux, const float* __restrict__ lbp,
              int M, int N, int K)
{
    __shared__ float As[8][128];
    __shared__ float Bs[8][128];

    const int t  = threadIdx.x;
    const int bm = blockIdx.y * 128;
    const int bn = blockIdx.x * 128;

    const int a_row = t >> 1;          // 0..127
    const int a_col = (t & 1) << 2;    // 0 or 4
    const int b_row = t >> 5;          // 0..7
    const int b_col = (t & 31) << 2;   // 0..124

    const int tm = (t >> 4) << 3;      // 0..120
    const int tn = (t & 15) << 3;      // 0..120

    const float* Ag = A + (size_t)(bm + a_row) * K + a_col;
    const float* Bg = W + (size_t)b_row * N + bn + b_col;

    float acc[8][8];
#pragma unroll
    for (int i = 0; i < 8; i++)
#pragma unroll
        for (int j = 0; j < 8; j++) acc[i][j] = 0.f;

    for (int k0 = 0; k0 < K; k0 += 8) {
        float4 av = *(const float4*)(Ag + k0);
        float4 bv = *(const float4*)(Bg + (size_t)k0 * N);
        As[a_col + 0][a_row] = av.x;
        As[a_col + 1][a_row] = av.y;
        As[a_col + 2][a_row] = av.z;
        As[a_col + 3][a_row] = av.w;
        *(float4*)&Bs[b_row][b_col] = bv;
        __syncthreads();
#pragma unroll
        for (int kk = 0; kk < 8; kk++) {
            float ar[8], br[8];
            *(float4*)&ar[0] = *(const float4*)&As[kk][tm];
            *(float4*)&ar[4] = *(const float4*)&As[kk][tm + 4];
            *(float4*)&br[0] = *(const float4*)&Bs[kk][tn];
            *(float4*)&br[4] = *(const float4*)&Bs[kk][tn + 4];
#pragma unroll
            for (int i = 0; i < 8; i++)
#pragma unroll
                for (int j = 0; j < 8; j++)
                    acc[i][j] = fmaf(ar[i], br[j], acc[i][j]);
        }
        __syncthreads();
    }

    float lb = 0.f;
    if (MODE == MODE_LAM) lb = __ldg(lbp);  // int32 0 and fp32 0.0 are bitwise equal

#pragma unroll
    for (int i = 0; i < 8; i++) {
        const size_t row = (size_t)(bm + tm + i);
        float* Crow = C + row * N + bn + tn;
        const float* auxrow =
            (MODE == MODE_U || MODE == MODE_GLU) ? (aux + row * N + bn + tn) : nullptr;
#pragma unroll
        for (int j0 = 0; j0 < 8; j0 += 4) {
            float rv[4];
#pragma unroll
            for (int k = 0; k < 4; k++) {
                const int j = j0 + k;
                float v = acc[i][j] + bias[bn + tn + j];
                if (MODE == MODE_PLAIN) {
                    rv[k] = v;
                } else if (MODE == MODE_SIG) {
                    rv[k] = sigmoidf_(v);
                } else if (MODE == MODE_LAM) {
                    rv[k] = lb + (1.f - lb) * sigmoidf_(v);
                } else if (MODE == MODE_U) {
                    float a = auxrow[j];
                    rv[k] = (1.f - a) * (v * sigmoidf_(v));   // (1-lam)*silu(i)
                } else {  // MODE_GLU
                    float a = auxrow[j];
                    rv[k] = (v * sigmoidf_(v)) * a;           // silu(xW1+b1) * (xW2+b2)
                }
            }
            float4 r;
            r.x = rv[0]; r.y = rv[1]; r.z = rv[2]; r.w = rv[3];
            *(float4*)(Crow + j0) = r;
        }
    }
}

// ---------------- forward + backward linear recurrence ----------------------
// h[t] = fwd_scan + bwd_scan of (h = lam*h_prev + u) over axis t, per (b,d)
__global__ void scan_fb(const float* __restrict__ lam, const float* __restrict__ u,
                        float* __restrict__ h)
{
    const int c = blockIdx.x * blockDim.x + threadIdx.x;
    if (c >= BSZ * DIM) return;
    const int b = c / DIM, d = c % DIM;
    const size_t base = (size_t)b * SEQ * DIM + d;

    float hf = 0.f;
#pragma unroll 4
    for (int t = 0; t < SEQ; t++) {
        const size_t idx = base + (size_t)t * DIM;
        hf = fmaf(lam[idx], hf, u[idx]);
        h[idx] = hf;
    }
    float hb = 0.f;
#pragma unroll 4
    for (int t = SEQ - 1; t >= 0; t--) {
        const size_t idx = base + (size_t)t * DIM;
        hb = fmaf(lam[idx], hb, u[idx]);
        h[idx] += hb;
    }
}

// ---------------- RMS-norm (param-free) * output gate -----------------------
__global__ void rms_gate(const float* __restrict__ h, const float* __restrict__ g,
                         float* __restrict__ out)
{
    const int row  = blockIdx.x * 8 + (threadIdx.x >> 5);
    const int lane = threadIdx.x & 31;
    const float* hr = h + (size_t)row * DIM;

    float4 v[4];
    float ss = 0.f;
#pragma unroll
    for (int i = 0; i < 4; i++) {
        v[i] = *(const float4*)(hr + i * 128 + lane * 4);
        ss += v[i].x * v[i].x + v[i].y * v[i].y + v[i].z * v[i].z + v[i].w * v[i].w;
    }
#pragma unroll
    for (int o = 16; o > 0; o >>= 1) ss += __shfl_xor_sync(0xffffffffu, ss, o);
    const float scale = rsqrtf(ss * (1.f / DIM) + 1e-6f);

    const float* gr  = g + (size_t)row * DIM;
    float* outr      = out + (size_t)row * DIM;
#pragma unroll
    for (int i = 0; i < 4; i++) {
        float4 gv = *(const float4*)(gr + i * 128 + lane * 4);
        float4 r;
        r.x = v[i].x * scale * gv.x;
        r.y = v[i].y * scale * gv.y;
        r.z = v[i].z * scale * gv.z;
        r.w = v[i].w * scale * gv.w;
        *(float4*)(outr + i * 128 + lane * 4) = r;
    }
}

// ---------------- out = resid + LayerNorm(y) * gam + bet --------------------
__global__ void ln_add(const float* __restrict__ y, const float* __restrict__ resid,
                       const float* __restrict__ gam, const float* __restrict__ bet,
                       float* __restrict__ out)
{
    const int row  = blockIdx.x * 8 + (threadIdx.x >> 5);
    const int lane = threadIdx.x & 31;
    const float* yr = y + (size_t)row * DIM;

    float4 v[4];
    float s1 = 0.f, s2 = 0.f;
#pragma unroll
    for (int i = 0; i < 4; i++) {
        v[i] = *(const float4*)(yr + i * 128 + lane * 4);
        s1 += v[i].x + v[i].y + v[i].z + v[i].w;
        s2 += v[i].x * v[i].x + v[i].y * v[i].y + v[i].z * v[i].z + v[i].w * v[i].w;
    }
#pragma unroll
    for (int o = 16; o > 0; o >>= 1) {
        s1 += __shfl_xor_sync(0xffffffffu, s1, o);
        s2 += __shfl_xor_sync(0xffffffffu, s2, o);
    }
    const float mean = s1 * (1.f / DIM);
    const float var  = s2 * (1.f / DIM) - mean * mean;
    const float inv  = rsqrtf(var + 1e-5f);

    const float* rr = resid + (size_t)row * DIM;
    float* outr     = out + (size_t)row * DIM;
#pragma unroll
    for (int i = 0; i < 4; i++) {
        const int col = i * 128 + lane * 4;
        float4 gv = *(const float4*)(gam + col);
        float4 bv = *(const float4*)(bet + col);
        float4 xv = *(const float4*)(rr + col);
        float4 r;
        r.x = xv.x + (v[i].x - mean) * inv * gv.x + bv.x;
        r.y = xv.y + (v[i].y - mean) * inv * gv.y + bv.y;
        r.z = xv.z + (v[i].z - mean) * inv * gv.z + bv.z;
        r.w = xv.w + (v[i].w - mean) * inv * gv.w + bv.w;
        *(float4*)(outr + col) = r;
    }
}

// ---------------- launcher ---------------------------------------------------
extern "C" void kernel_launch(void* const* d_in, const int* in_sizes, int n_in,
                              void* d_out, int out_size)
{
    const float* x    = (const float*)d_in[0];
    const float* lbp  = (const float*)d_in[1];
    const float* Wi   = (const float*)d_in[2];
    const float* bi   = (const float*)d_in[3];
    const float* Wf   = (const float*)d_in[4];
    const float* bf   = (const float*)d_in[5];
    const float* Wg   = (const float*)d_in[6];
    const float* bg   = (const float*)d_in[7];
    const float* Wo   = (const float*)d_in[8];
    const float* bo   = (const float*)d_in[9];
    const float* tn_g = (const float*)d_in[10];
    const float* tn_b = (const float*)d_in[11];
    const float* fn_g = (const float*)d_in[12];
    const float* fn_b = (const float*)d_in[13];
    const float* W1   = (const float*)d_in[14];
    const float* b1   = (const float*)d_in[15];
    const float* W2   = (const float*)d_in[16];
    const float* b2   = (const float*)d_in[17];
    const float* W3   = (const float*)d_in[18];
    const float* b3   = (const float*)d_in[19];
    float* out = (float*)d_out;

    float *bA, *bB, *bC, *bD, *bE, *bF;
    cudaGetSymbolAddress((void**)&bA, g_bufA);
    cudaGetSymbolAddress((void**)&bB, g_bufB);
    cudaGetSymbolAddress((void**)&bC, g_bufC);
    cudaGetSymbolAddress((void**)&bD, g_bufD);
    cudaGetSymbolAddress((void**)&bE, g_bufE);
    cudaGetSymbolAddress((void**)&bF, g_bufF);

    dim3 blk(256);
    dim3 gD(DIM / 128, MROWS / 128);    // (4, 512)
    dim3 gG(DGLU / 128, MROWS / 128);   // (8, 512)
    const int rowsBlocks = MROWS / 8;   // 8192 (warp per row)

    // lam = lb + (1-lb)*sigmoid(x@Wf + bf)
    sgemm_ep<MODE_LAM><<<gD, blk>>>(x, Wf, bf, bA, nullptr, lbp, MROWS, DIM, DIM);
    // u = (1-lam)*silu(x@Wi + bi)
    sgemm_ep<MODE_U><<<gD, blk>>>(x, Wi, bi, bB, bA, nullptr, MROWS, DIM, DIM);
    // g = sigmoid(x@Wg + bg)
    sgemm_ep<MODE_SIG><<<gD, blk>>>(x, Wg, bg, bC, nullptr, nullptr, MROWS, DIM, DIM);
    // h = fwd_scan(lam,u) + bwd_scan(lam,u)
    scan_fb<<<(BSZ * DIM + 255) / 256, 256>>>(bA, bB, bD);
    // hg = rmsnorm(h) * g   -> bA (lam dead)
    rms_gate<<<rowsBlocks, 256>>>(bD, bC, bA);
    // y1 = hg @ Wo + bo     -> bB
    sgemm_ep<MODE_PLAIN><<<gD, blk>>>(bA, Wo, bo, bB, nullptr, nullptr, MROWS, DIM, DIM);
    // x1 = x + LN(y1)       -> bC
    ln_add<<<rowsBlocks, 256>>>(bB, x, tn_g, tn_b, bC);
    // c = x1 @ W2 + b2      -> bE
    sgemm_ep<MODE_PLAIN><<<gG, blk>>>(bC, W2, b2, bE, nullptr, nullptr, MROWS, DGLU, DIM);
    // p = silu(x1 @ W1 + b1) * c  -> bF
    sgemm_ep<MODE_GLU><<<gG, blk>>>(bC, W1, b1, bF, bE, nullptr, MROWS, DGLU, DIM);
    // y2 = p @ W3 + b3      -> bA
    sgemm_ep<MODE_PLAIN><<<gD, blk>>>(bF, W3, b3, bA, nullptr, nullptr, MROWS, DIM, DGLU);
    // out = x1 + LN(y2)
    ln_add<<<rowsBlocks, 256>>>(bA, bC, fn_g, fn_b, out);
}

// round 2
// speedup vs baseline: 1.0004x; 1.0004x over previous
#include <cuda_runtime.h>
#include <math.h>

#define BSZ   32
#define SEQ   2048
#define DIM   512
#define DGLU  1024
#define MROWS (BSZ * SEQ)   // 65536

// ---------------- scratch (device globals; no allocation allowed) ----------
__device__ float g_bufA[(size_t)MROWS * DIM];
__device__ float g_bufB[(size_t)MROWS * DIM];
__device__ float g_bufC[(size_t)MROWS * DIM];
__device__ float g_bufD[(size_t)MROWS * DIM];
__device__ float g_bufE[(size_t)MROWS * DGLU];
__device__ float g_bufF[(size_t)MROWS * DGLU];

__device__ __forceinline__ float sigmoidf_(float v) { return 1.f / (1.f + expf(-v)); }

enum { MODE_PLAIN = 0, MODE_SIG = 1, MODE_LAM = 2, MODE_U = 3, MODE_GLU = 4 };

// ---------------- 128x128x8 fp32 GEMM with fused epilogue -------------------
// C[M,N] = epilogue(A[M,K] @ W[K,N] + bias[N])
template <int MODE>
__global__ __launch_bounds__(256, 2)
void sgemm_ep(const float* __restrict__ A, const float* __restrict__ W,
              const float* __restrict__ bias, float* __restrict__ C,
              const float* __restrict__ aux, const float* __restrict__ lbp,
              int M, int N, int K)
{
    __shared__ float As[8][128];
    __shared__ float Bs[8][128];

    const int t  = threadIdx.x;
    const int bm = blockIdx.y * 128;
    const int bn = blockIdx.x * 128;

    const int a_row = t >> 1;          // 0..127
    const int a_col = (t & 1) << 2;    // 0 or 4
    const int b_row = t >> 5;          // 0..7
    const int b_col = (t & 31) << 2;   // 0..124

    const int tm = (t >> 4) << 3;      // 0..120
    const int tn = (t & 15) << 3;      // 0..120

    const float* Ag = A + (size_t)(bm + a_row) * K + a_col;
    const float* Bg = W + (size_t)b_row * N + bn + b_col;

    float acc[8][8];
#pragma unroll
    for (int i = 0; i < 8; i++)
#pragma unroll
        for (int j = 0; j < 8; j++) acc[i][j] = 0.f;

    for (int k0 = 0; k0 < K; k0 += 8) {
        float4 av = *(const float4*)(Ag + k0);
        float4 bv = *(const float4*)(Bg + (size_t)k0 * N);
        As[a_col + 0][a_row] = av.x;
        As[a_col + 1][a_row] = av.y;
        As[a_col + 2][a_row] = av.z;
        As[a_col + 3][a_row] = av.w;
        *(float4*)&Bs[b_row][b_col] = bv;
        __syncthreads();
#pragma unroll
        for (int kk = 0; kk < 8; kk++) {
            float ar[8], br[8];
            *(float4*)&ar[0] = *(const float4*)&As[kk][tm];
            *(float4*)&ar[4] = *(const float4*)&As[kk][tm + 4];
            *(float4*)&br[0] = *(const float4*)&Bs[kk][tn];
            *(float4*)&br[4] = *(const float4*)&Bs[kk][tn + 4];
#pragma unroll
            for (int i = 0; i < 8; i++)
#pragma unroll
                for (int j = 0; j < 8; j++)
                    acc[i][j] = fmaf(ar[i], br[j], acc[i][j]);
        }
        __syncthreads();
    }

    float lb = 0.f;
    if (MODE == MODE_LAM) lb = __ldg(lbp);  // int32 0 and fp32 0.0 are bitwise equal

#pragma unroll
    for (int i = 0; i < 8; i++) {
        const size_t row = (size_t)(bm + tm + i);
        float* Crow = C + row * N + bn + tn;
        const float* auxrow =
            (MODE == MODE_U || MODE == MODE_GLU) ? (aux + row * N + bn + tn) : nullptr;
#pragma unroll
        for (int j0 = 0; j0 < 8; j0 += 4) {
            float rv[4];
#pragma unroll
            for (int k = 0; k < 4; k++) {
                const int j = j0 + k;
                float v = acc[i][j] + bias[bn + tn + j];
                if (MODE == MODE_PLAIN) {
                    rv[k] = v;
                } else if (MODE == MODE_SIG) {
                    rv[k] = sigmoidf_(v);
                } else if (MODE == MODE_LAM) {
                    rv[k] = lb + (1.f - lb) * sigmoidf_(v);
                } else if (MODE == MODE_U) {
                    float a = auxrow[j];
                    rv[k] = (1.f - a) * (v * sigmoidf_(v));   // (1-lam)*silu(i)
                } else {  // MODE_GLU
                    float a = auxrow[j];
                    rv[k] = (v * sigmoidf_(v)) * a;           // silu(xW1+b1) * (xW2+b2)
                }
            }
            float4 r;
            r.x = rv[0]; r.y = rv[1]; r.z = rv[2]; r.w = rv[3];
            *(float4*)(Crow + j0) = r;
        }
    }
}

// ---------------- forward + backward linear recurrence ----------------------
// h[t] = fwd_scan + bwd_scan of (h = lam*h_prev + u) over axis t, per (b,d)
__global__ void scan_fb(const float* __restrict__ lam, const float* __restrict__ u,
                        float* __restrict__ h)
{
    const int c = blockIdx.x * blockDim.x + threadIdx.x;
    if (c >= BSZ * DIM) return;
    const int b = c / DIM, d = c % DIM;
    const size_t base = (size_t)b * SEQ * DIM + d;

    float hf = 0.f;
#pragma unroll 4
    for (int t = 0; t < SEQ; t++) {
        const size_t idx = base + (size_t)t * DIM;
        hf = fmaf(lam[idx], hf, u[idx]);
        h[idx] = hf;
    }
    float hb = 0.f;
#pragma unroll 4
    for (int t = SEQ - 1; t >= 0; t--) {
        const size_t idx = base + (size_t)t * DIM;
        hb = fmaf(lam[idx], hb, u[idx]);
        h[idx] += hb;
    }
}

// ---------------- RMS-norm (param-free) * output gate -----------------------
__global__ void rms_gate(const float* __restrict__ h, const float* __restrict__ g,
                         float* __restrict__ out)
{
    const int row  = blockIdx.x * 8 + (threadIdx.x >> 5);
    const int lane = threadIdx.x & 31;
    const float* hr = h + (size_t)row * DIM;

    float4 v[4];
    float ss = 0.f;
#pragma unroll
    for (int i = 0; i < 4; i++) {
        v[i] = *(const float4*)(hr + i * 128 + lane * 4);
        ss += v[i].x * v[i].x + v[i].y * v[i].y + v[i].z * v[i].z + v[i].w * v[i].w;
    }
#pragma unroll
    for (int o = 16; o > 0; o >>= 1) ss += __shfl_xor_sync(0xffffffffu, ss, o);
    const float scale = rsqrtf(ss * (1.f / DIM) + 1e-6f);

    const float* gr  = g + (size_t)row * DIM;
    float* outr      = out + (size_t)row * DIM;
#pragma unroll
    for (int i = 0; i < 4; i++) {
        float4 gv = *(const float4*)(gr + i * 128 + lane * 4);
        float4 r;
        r.x = v[i].x * scale * gv.x;
        r.y = v[i].y * scale * gv.y;
        r.z = v[i].z * scale * gv.z;
        r.w = v[i].w * scale * gv.w;
        *(float4*)(outr + i * 128 + lane * 4) = r;
    }
}

// ---------------- out = resid + LayerNorm(y) * gam + bet --------------------
__global__ void ln_add(const float* __restrict__ y, const float* __restrict__ resid,
                       const float* __restrict__ gam, const float* __restrict__ bet,
                       float* __restrict__ out)
{
    const int row  = blockIdx.x * 8 + (threadIdx.x >> 5);
    const int lane = threadIdx.x & 31;
    const float* yr = y + (size_t)row * DIM;

    float4 v[4];
    float s1 = 0.f, s2 = 0.f;
#pragma unroll
    for (int i = 0; i < 4; i++) {
        v[i] = *(const float4*)(yr + i * 128 + lane * 4);
        s1 += v[i].x + v[i].y + v[i].z + v[i].w;
        s2 += v[i].x * v[i].x + v[i].y * v[i].y + v[i].z * v[i].z + v[i].w * v[i].w;
    }
#pragma unroll
    for (int o = 16; o > 0; o >>= 1) {
        s1 += __shfl_xor_sync(0xffffffffu, s1, o);
        s2 += __shfl_xor_sync(0xffffffffu, s2, o);
    }
    const float mean = s1 * (1.f / DIM);
    const float var  = s2 * (1.f / DIM) - mean * mean;
    const float inv  = rsqrtf(var + 1e-5f);

    const float* rr = resid + (size_t)row * DIM;
    float* outr     = out + (size_t)row * DIM;
#pragma unroll
    for (int i = 0; i < 4; i++) {
        const int col = i * 128 + lane * 4;
        float4 gv = *(const float4*)(gam + col);
        float4 bv = *(const float4*)(bet + col);
        float4 xv = *(const float4*)(rr + col);
        float4 r;
        r.x = xv.x + (v[i].x - mean) * inv * gv.x + bv.x;
        r.y = xv.y + (v[i].y - mean) * inv * gv.y + bv.y;
        r.z = xv.z + (v[i].z - mean) * inv * gv.z + bv.z;
        r.w = xv.w + (v[i].w - mean) * inv * gv.w + bv.w;
        *(float4*)(outr + col) = r;
    }
}

// ---------------- launcher ---------------------------------------------------
extern "C" void kernel_launch(void* const* d_in, const int* in_sizes, int n_in,
                              void* d_out, int out_size)
{
    const float* x    = (const float*)d_in[0];
    const float* lbp  = (const float*)d_in[1];
    const float* Wi   = (const float*)d_in[2];
    const float* bi   = (const float*)d_in[3];
    const float* Wf   = (const float*)d_in[4];
    const float* bf   = (const float*)d_in[5];
    const float* Wg   = (const float*)d_in[6];
    const float* bg   = (const float*)d_in[7];
    const float* Wo   = (const float*)d_in[8];
    const float* bo   = (const float*)d_in[9];
    const float* tn_g = (const float*)d_in[10];
    const float* tn_b = (const float*)d_in[11];
    const float* fn_g = (const float*)d_in[12];
    const float* fn_b = (const float*)d_in[13];
    const float* W1   = (const float*)d_in[14];
    const float* b1   = (const float*)d_in[15];
    const float* W2   = (const float*)d_in[16];
    const float* b2   = (const float*)d_in[17];
    const float* W3   = (const float*)d_in[18];
    const float* b3   = (const float*)d_in[19];
    float* out = (float*)d_out;

    float *bA, *bB, *bC, *bD, *bE, *bF;
    cudaGetSymbolAddress((void**)&bA, g_bufA);
    cudaGetSymbolAddress((void**)&bB, g_bufB);
    cudaGetSymbolAddress((void**)&bC, g_bufC);
    cudaGetSymbolAddress((void**)&bD, g_bufD);
    cudaGetSymbolAddress((void**)&bE, g_bufE);
    cudaGetSymbolAddress((void**)&bF, g_bufF);

    dim3 blk(256);
    dim3 gD(DIM / 128, MROWS / 128);    // (4, 512)
    dim3 gG(DGLU / 128, MROWS / 128);   // (8, 512)
    const int rowsBlocks = MROWS / 8;   // 8192 (warp per row)

    // lam = lb + (1-lb)*sigmoid(x@Wf + bf)
    sgemm_ep<MODE_LAM><<<gD, blk>>>(x, Wf, bf, bA, nullptr, lbp, MROWS, DIM, DIM);
    // u = (1-lam)*silu(x@Wi + bi)
    sgemm_ep<MODE_U><<<gD, blk>>>(x, Wi, bi, bB, bA, nullptr, MROWS, DIM, DIM);
    // g = sigmoid(x@Wg + bg)
    sgemm_ep<MODE_SIG><<<gD, blk>>>(x, Wg, bg, bC, nullptr, nullptr, MROWS, DIM, DIM);
    // h = fwd_scan(lam,u) + bwd_scan(lam,u)
    scan_fb<<<(BSZ * DIM + 255) / 256, 256>>>(bA, bB, bD);
    // hg = rmsnorm(h) * g   -> bA (lam dead)
    rms_gate<<<rowsBlocks, 256>>>(bD, bC, bA);
    // y1 = hg @ Wo + bo     -> bB
    sgemm_ep<MODE_PLAIN><<<gD, blk>>>(bA, Wo, bo, bB, nullptr, nullptr, MROWS, DIM, DIM);
    // x1 = x + LN(y1)       -> bC
    ln_add<<<rowsBlocks, 256>>>(bB, x, tn_g, tn_b, bC);
    // c = x1 @ W2 + b2      -> bE
    sgemm_ep<MODE_PLAIN><<<gG, blk>>>(bC, W2, b2, bE, nullptr, nullptr, MROWS, DGLU, DIM);
    // p = silu(x1 @ W1 + b1) * c  -> bF
    sgemm_ep<MODE_GLU><<<gG, blk>>>(bC, W1, b1, bF, bE, nullptr, MROWS, DGLU, DIM);
    // y2 = p @ W3 + b3      -> bA
    sgemm_ep<MODE_PLAIN><<<gD, blk>>>(bF, W3, b3, bA, nullptr, nullptr, MROWS, DIM, DGLU);
    // out = x1 + LN(y2)
    ln_add<<<rowsBlocks, 256>>>(bA, bC, fn_g, fn_b, out);
}

// round 4
// speedup vs baseline: 1.6753x; 1.6746x over previous
#include <cuda_runtime.h>
#include <math.h>
#include <stdint.h>

#define BSZ 32
#define SEQ 2048
#define DIM 512
#define DGLU 1024
#define MROWS (BSZ * SEQ)
#define SCAN_TS 32
#define SCAN_CH (SEQ / SCAN_TS)

#define SROW 20            // padded floats per smem row (BK=16 + 4)
#define TILE (128 * SROW)  // 2560 floats
#define BUFSZ (2 * TILE)   // A tile + B tile

__device__ float g_bufA[(size_t)MROWS * DIM];
__device__ float g_bufB[(size_t)MROWS * DIM];
__device__ float g_bufC[(size_t)MROWS * DIM];
__device__ float g_bufD[(size_t)MROWS * DIM];
__device__ float g_bufE[(size_t)MROWS * DGLU];
__device__ float g_bufF[(size_t)MROWS * DGLU];
__device__ float g_WT[2621440];

__device__ __forceinline__ float sigmoidf_(float v) { return 1.f / (1.f + expf(-v)); }

enum { MODE_PLAIN = 0, MODE_SIG = 1, MODE_LAM = 2, MODE_U = 3, MODE_GLU = 4 };

__device__ __forceinline__ uint32_t f2tf32(float f) {
    uint32_t u; asm("cvt.rna.tf32.f32 %0, %1;" : "=r"(u) : "f"(f)); return u;
}
__device__ __forceinline__ void mma_tf32(float* d, const uint32_t* a, const uint32_t* b) {
    asm volatile("mma.sync.aligned.m16n8k8.row.col.f32.tf32.tf32.f32 "
                 "{%0,%1,%2,%3}, {%4,%5,%6,%7}, {%8,%9}, {%0,%1,%2,%3};"
                 : "+f"(d[0]), "+f"(d[1]), "+f"(d[2]), "+f"(d[3])
                 : "r"(a[0]), "r"(a[1]), "r"(a[2]), "r"(a[3]), "r"(b[0]), "r"(b[1]));
}

// stage one 128x16 chunk of A and B from global into regs
__device__ __forceinline__ void ldg_chunk(const float* Ab, const float* Bb, int K, int kc,
                                          int tid, float4* ra, float4* rb) {
#pragma unroll
    for (int i = 0; i < 2; i++) {
        const int row = tid & 127, c4 = (tid >> 7) + 2 * i;
        ra[i] = *(const float4*)(Ab + (size_t)row * K + kc * 16 + c4 * 4);
        rb[i] = *(const float4*)(Bb + (size_t)row * K + kc * 16 + c4 * 4);
    }
}
__device__ __forceinline__ void sts_chunk(float* As, float* Bs, int tid,
                                          const float4* ra, const float4* rb) {
#pragma unroll
    for (int i = 0; i < 2; i++) {
        const int row = tid & 127, c4 = (tid >> 7) + 2 * i;
        uint4 at, bt;
        at.x = f2tf32(ra[i].x); at.y = f2tf32(ra[i].y); at.z = f2tf32(ra[i].z); at.w = f2tf32(ra[i].w);
        bt.x = f2tf32(rb[i].x); bt.y = f2tf32(rb[i].y); bt.z = f2tf32(rb[i].z); bt.w = f2tf32(rb[i].w);
        *(uint4*)(As + row * SROW + c4 * 4) = at;
        *(uint4*)(Bs + row * SROW + c4 * 4) = bt;
    }
}

// C[M,N] = epilogue(A[M,K] @ WT[N,K]^T + bias)
template <int MODE>
__global__ __launch_bounds__(256)
void tc_gemm(const float* __restrict__ A, const float* __restrict__ WT,
             const float* __restrict__ bias, float* __restrict__ C,
             const float* __restrict__ aux, const float* __restrict__ lbp, int N, int K)
{
    __shared__ float sm[2 * BUFSZ];   // 40 KB

    const int tid = threadIdx.x, wid = tid >> 5, lane = tid & 31;
    const int g = lane >> 2, cc = lane & 3;
    const int bm = blockIdx.y * 128, bn = blockIdx.x * 128;
    const int wm = (wid >> 2) * 64, wn = (wid & 3) * 32;

    const float* Ab = A + (size_t)bm * K;
    const float* Bb = WT + (size_t)bn * K;
    const int NK = K >> 4;

    float acc[4][4][4];
#pragma unroll
    for (int mf = 0; mf < 4; mf++)
#pragma unroll
        for (int nf = 0; nf < 4; nf++)
#pragma unroll
            for (int k = 0; k < 4; k++) acc[mf][nf][k] = 0.f;

    float4 ra[2], rb[2];
    ldg_chunk(Ab, Bb, K, 0, tid, ra, rb);
    sts_chunk(sm, sm + TILE, tid, ra, rb);
    __syncthreads();

    for (int kc = 0; kc < NK; kc++) {
        if (kc + 1 < NK) ldg_chunk(Ab, Bb, K, kc + 1, tid, ra, rb);
        const float* As = sm + (kc & 1) * BUFSZ;
        const float* Bs = As + TILE;
#pragma unroll
        for (int ks = 0; ks < 2; ks++) {
            uint32_t af[4][4], bf[4][2];
#pragma unroll
            for (int mf = 0; mf < 4; mf++) {
                const float* p = As + (wm + mf * 16 + g) * SROW + ks * 8 + cc;
                af[mf][0] = __float_as_uint(p[0]);
                af[mf][1] = __float_as_uint(p[8 * SROW]);
                af[mf][2] = __float_as_uint(p[4]);
                af[mf][3] = __float_as_uint(p[8 * SROW + 4]);
            }
#pragma unroll
            for (int nf = 0; nf < 4; nf++) {
                const float* q = Bs + (wn + nf * 8 + g) * SROW + ks * 8 + cc;
                bf[nf][0] = __float_as_uint(q[0]);
                bf[nf][1] = __float_as_uint(q[4]);
            }
#pragma unroll
            for (int mf = 0; mf < 4; mf++)
#pragma unroll
                for (int nf = 0; nf < 4; nf++)
                    mma_tf32(acc[mf][nf], af[mf], bf[nf]);
        }
        if (kc + 1 < NK) sts_chunk(sm + ((kc + 1) & 1) * BUFSZ,
                                   sm + ((kc + 1) & 1) * BUFSZ + TILE, tid, ra, rb);
        __syncthreads();
    }

    float lb = 0.f;
    if (MODE == MODE_LAM) lb = __ldg(lbp);

#pragma unroll
    for (int mf = 0; mf < 4; mf++) {
#pragma unroll
        for (int half = 0; half < 2; half++) {
            const int row = bm + wm + mf * 16 + g + half * 8;
            float* Crow = C + (size_t)row * N;
            const float* Arow = (MODE == MODE_U || MODE == MODE_GLU)
                                ? aux + (size_t)row * N : nullptr;
#pragma unroll
            for (int nf = 0; nf < 4; nf++) {
                const int col = bn + wn + nf * 8 + cc * 2;
                const float2 bb = *(const float2*)&bias[col];
                float v0 = acc[mf][nf][half * 2 + 0] + bb.x;
                float v1 = acc[mf][nf][half * 2 + 1] + bb.y;
                float o0, o1;
                if (MODE == MODE_PLAIN) {
                    o0 = v0; o1 = v1;
                } else if (MODE == MODE_SIG) {
                    o0 = sigmoidf_(v0); o1 = sigmoidf_(v1);
                } else if (MODE == MODE_LAM) {
                    o0 = lb + (1.f - lb) * sigmoidf_(v0);
                    o1 = lb + (1.f - lb) * sigmoidf_(v1);
                } else if (MODE == MODE_U) {
                    const float2 ax = *(const float2*)(Arow + col);
                    o0 = (1.f - ax.x) * (v0 * sigmoidf_(v0));
                    o1 = (1.f - ax.y) * (v1 * sigmoidf_(v1));
                } else {
                    const float2 ax = *(const float2*)(Arow + col);
                    o0 = (v0 * sigmoidf_(v0)) * ax.x;
                    o1 = (v1 * sigmoidf_(v1)) * ax.y;
                }
                float2 o; o.x = o0; o.y = o1;
                *(float2*)(Crow + col) = o;
            }
        }
    }
}

// dst[n*K+k] = src[k*N+n]
__global__ void transpose_w(const float* __restrict__ src, float* __restrict__ dst, int K, int N) {
    __shared__ float tile[32][33];
    const int n0 = blockIdx.x * 32, k0 = blockIdx.y * 32;
    for (int i = threadIdx.y; i < 32; i += 8)
        tile[i][threadIdx.x] = src[(size_t)(k0 + i) * N + n0 + threadIdx.x];
    __syncthreads();
    for (int i = threadIdx.y; i < 32; i += 8)
        dst[(size_t)(n0 + i) * K + k0 + threadIdx.x] = tile[threadIdx.x][i];
}

__global__ __launch_bounds__(512)
void scan_pass1(const float* __restrict__ lam, const float* __restrict__ u,
                float* __restrict__ lF, float* __restrict__ lB,
                float* __restrict__ prod, float* __restrict__ lastF, float* __restrict__ lastB)
{
    const int b = blockIdx.x >> 6, ch = blockIdx.x & 63;
    const int d = threadIdx.x;
    const size_t base = ((size_t)b * SEQ + ch * SCAN_TS) * DIM + d;
    float hf = 0.f, p = 1.f;
#pragma unroll 4
    for (int t = 0; t < SCAN_TS; t++) {
        const size_t ix = base + (size_t)t * DIM;
        const float l = lam[ix];
        hf = fmaf(l, hf, u[ix]); p *= l; lF[ix] = hf;
    }
    float hb = 0.f;
#pragma unroll 4
    for (int t = SCAN_TS - 1; t >= 0; t--) {
        const size_t ix = base + (size_t)t * DIM;
        hb = fmaf(lam[ix], hb, u[ix]); lB[ix] = hb;
    }
    const int ci = (b * SCAN_CH + ch) * DIM + d;
    prod[ci] = p; lastF[ci] = hf; lastB[ci] = hb;
}

__global__ void scan_pass2(const float* __restrict__ prod, const float* __restrict__ lastF,
                           const float* __restrict__ lastB, float* __restrict__ CF, float* __restrict__ CB)
{
    const int c = blockIdx.x * blockDim.x + threadIdx.x;
    if (c >= BSZ * DIM) return;
    const int b = c >> 9, d = c & 511;
    float cf = 0.f;
    for (int ch = 0; ch < SCAN_CH; ch++) {
        const int i = (b * SCAN_CH + ch) * DIM + d;
        CF[i] = cf; cf = fmaf(prod[i], cf, lastF[i]);
    }
    float cb = 0.f;
    for (int ch = SCAN_CH - 1; ch >= 0; ch--) {
        const int i = (b * SCAN_CH + ch) * DIM + d;
        CB[i] = cb; cb = fmaf(prod[i], cb, lastB[i]);
    }
}

__global__ __launch_bounds__(512)
void scan_pass3(const float* __restrict__ lam, const float* __restrict__ lF,
                const float* __restrict__ lB, const float* __restrict__ CF,
                const float* __restrict__ CB, float* __restrict__ h)
{
    const int b = blockIdx.x >> 6, ch = blockIdx.x & 63;
    const int d = threadIdx.x;
    const size_t base = ((size_t)b * SEQ + ch * SCAN_TS) * DIM + d;
    const int ci = (b * SCAN_CH + ch) * DIM + d;
    const float cf = CF[ci], cb = CB[ci];
    float vals[SCAN_TS];
    float p = 1.f;
#pragma unroll
    for (int t = 0; t < SCAN_TS; t++) {
        const size_t ix = base + (size_t)t * DIM;
        p *= lam[ix];
        vals[t] = fmaf(cf, p, lF[ix]);
    }
    float q = 1.f;
#pragma unroll
    for (int t = SCAN_TS - 1; t >= 0; t--) {
        const size_t ix = base + (size_t)t * DIM;
        q *= lam[ix];
        h[ix] = vals[t] + fmaf(cb, q, lB[ix]);
    }
}

__global__ void rms_gate(const float* __restrict__ h, const float* __restrict__ g, float* __restrict__ out) {
    const int row = blockIdx.x * 8 + (threadIdx.x >> 5), lane = threadIdx.x & 31;
    const float* hr = h + (size_t)row * DIM;
    float4 v[4]; float ss = 0.f;
#pragma unroll
    for (int i = 0; i < 4; i++) {
        v[i] = *(const float4*)(hr + i * 128 + lane * 4);
        ss += v[i].x * v[i].x + v[i].y * v[i].y + v[i].z * v[i].z + v[i].w * v[i].w;
    }
#pragma unroll
    for (int o = 16; o > 0; o >>= 1) ss += __shfl_xor_sync(0xffffffffu, ss, o);
    const float sc = rsqrtf(ss * (1.f / DIM) + 1e-6f);
    const float* gr = g + (size_t)row * DIM;
    float* outr = out + (size_t)row * DIM;
#pragma unroll
    for (int i = 0; i < 4; i++) {
        float4 gv = *(const float4*)(gr + i * 128 + lane * 4);
        float4 r;
        r.x = v[i].x * sc * gv.x; r.y = v[i].y * sc * gv.y;
        r.z = v[i].z * sc * gv.z; r.w = v[i].w * sc * gv.w;
        *(float4*)(outr + i * 128 + lane * 4) = r;
    }
}

__global__ void ln_add(const float* __restrict__ y, const float* __restrict__ resid,
                       const float* __restrict__ gam, const float* __restrict__ bet, float* __restrict__ out) {
    const int row = blockIdx.x * 8 + (threadIdx.x >> 5), lane = threadIdx.x & 31;
    const float* yr = y + (size_t)row * DIM;
    float4 v[4]; float s1 = 0.f, s2 = 0.f;
#pragma unroll
    for (int i = 0; i < 4; i++) {
        v[i] = *(const float4*)(yr + i * 128 + lane * 4);
        s1 += v[i].x + v[i].y + v[i].z + v[i].w;
        s2 += v[i].x * v[i].x + v[i].y * v[i].y + v[i].z * v[i].z + v[i].w * v[i].w;
    }
#pragma unroll
    for (int o = 16; o > 0; o >>= 1) {
        s1 += __shfl_xor_sync(0xffffffffu, s1, o);
        s2 += __shfl_xor_sync(0xffffffffu, s2, o);
    }
    const float mean = s1 * (1.f / DIM);
    const float inv = rsqrtf(s2 * (1.f / DIM) - mean * mean + 1e-5f);
    const float* rr = resid + (size_t)row * DIM;
    float* outr = out + (size_t)row * DIM;
#pragma unroll
    for (int i = 0; i < 4; i++) {
        const int col = i * 128 + lane * 4;
        float4 gv = *(const float4*)(gam + col);
        float4 bv = *(const float4*)(bet + col);
        float4 xv = *(const float4*)(rr + col);
        float4 r;
        r.x = xv.x + (v[i].x - mean) * inv * gv.x + bv.x;
        r.y = xv.y + (v[i].y - mean) * inv * gv.y + bv.y;
        r.z = xv.z + (v[i].z - mean) * inv * gv.z + bv.z;
        r.w = xv.w + (v[i].w - mean) * inv * gv.w + bv.w;
        *(float4*)(outr + col) = r;
    }
}

extern "C" void kernel_launch(void* const* d_in, const int* in_sizes, int n_in,
                              void* d_out, int out_size)
{
    const float* x = (const float*)d_in[0];
    const float* lbp = (const float*)d_in[1];
    const float* Wi = (const float*)d_in[2];  const float* bi = (const float*)d_in[3];
    const float* Wf = (const float*)d_in[4];  const float* bf = (const float*)d_in[5];
    const float* Wg = (const float*)d_in[6];  const float* bg = (const float*)d_in[7];
    const float* Wo = (const float*)d_in[8];  const float* bo = (const float*)d_in[9];
    const float* tn_g = (const float*)d_in[10]; const float* tn_b = (const float*)d_in[11];
    const float* fn_g = (const float*)d_in[12]; const float* fn_b = (const float*)d_in[13];
    const float* W1 = (const float*)d_in[14]; const float* b1 = (const float*)d_in[15];
    const float* W2 = (const float*)d_in[16]; const float* b2 = (const float*)d_in[17];
    const float* W3 = (const float*)d_in[18]; const float* b3 = (const float*)d_in[19];
    float* out = (float*)d_out;

    float *bA, *bB, *bC, *bD, *bE, *bF, *wt;
    cudaGetSymbolAddress((void**)&bA, g_bufA);
    cudaGetSymbolAddress((void**)&bB, g_bufB);
    cudaGetSymbolAddress((void**)&bC, g_bufC);
    cudaGetSymbolAddress((void**)&bD, g_bufD);
    cudaGetSymbolAddress((void**)&bE, g_bufE);
    cudaGetSymbolAddress((void**)&bF, g_bufF);
    cudaGetSymbolAddress((void**)&wt, g_WT);

    float* WiT = wt;
    float* WfT = wt + 262144;
    float* WgT = wt + 524288;
    float* WoT = wt + 786432;
    float* W1T = wt + 1048576;
    float* W2T = wt + 1572864;
    float* W3T = wt + 2097152;

    float* lF = bE;
    float* lB = bF;
    float* prod  = bE + (size_t)MROWS * DIM;
    float* lastF = prod + (size_t)BSZ * SCAN_CH * DIM;
    float* lastB = lastF + (size_t)BSZ * SCAN_CH * DIM;
    float* CF = bF + (size_t)MROWS * DIM;
    float* CB = CF + (size_t)BSZ * SCAN_CH * DIM;

    dim3 tb(32, 8);
    transpose_w<<<dim3(16, 16), tb>>>(Wi, WiT, DIM, DIM);
    transpose_w<<<dim3(16, 16), tb>>>(Wf, WfT, DIM, DIM);
    transpose_w<<<dim3(16, 16), tb>>>(Wg, WgT, DIM, DIM);
    transpose_w<<<dim3(16, 16), tb>>>(Wo, WoT, DIM, DIM);
    transpose_w<<<dim3(32, 16), tb>>>(W1, W1T, DIM, DGLU);
    transpose_w<<<dim3(32, 16), tb>>>(W2, W2T, DIM, DGLU);
    transpose_w<<<dim3(16, 32), tb>>>(W3, W3T, DGLU, DIM);

    dim3 blk(256);
    dim3 gD(DIM / 128, MROWS / 128);
    dim3 gG(DGLU / 128, MROWS / 128);
    const int rowsBlocks = MROWS / 8;
    const int scanBlocks = BSZ * SCAN_CH;

    tc_gemm<MODE_LAM><<<gD, blk>>>(x, WfT, bf, bA, nullptr, lbp, DIM, DIM);
    tc_gemm<MODE_U><<<gD, blk>>>(x, WiT, bi, bB, bA, nullptr, DIM, DIM);
    tc_gemm<MODE_SIG><<<gD, blk>>>(x, WgT, bg, bC, nullptr, nullptr, DIM, DIM);
    scan_pass1<<<scanBlocks, DIM>>>(bA, bB, lF, lB, prod, lastF, lastB);
    scan_pass2<<<(BSZ * DIM + 255) / 256, 256>>>(prod, lastF, lastB, CF, CB);
    scan_pass3<<<scanBlocks, DIM>>>(bA, lF, lB, CF, CB, bD);
    rms_gate<<<rowsBlocks, 256>>>(bD, bC, bA);
    tc_gemm<MODE_PLAIN><<<gD, blk>>>(bA, WoT, bo, bB, nullptr, nullptr, DIM, DIM);
    ln_add<<<rowsBlocks, 256>>>(bB, x, tn_g, tn_b, bC);
    tc_gemm<MODE_PLAIN><<<gG, blk>>>(bC, W2T, b2, bE, nullptr, nullptr, DGLU, DIM);
    tc_gemm<MODE_GLU><<<gG, blk>>>(bC, W1T, b1, bF, bE, nullptr, DGLU, DIM);
    tc_gemm<MODE_PLAIN><<<gD, blk>>>(bF, W3T, b3, bA, nullptr, nullptr, DIM, DGLU);
    ln_add<<<rowsBlocks, 256>>>(bA, bC, fn_g, fn_b, out);
}

// round 5
// speedup vs baseline: 2.7490x; 1.6410x over previous
#include <cuda_runtime.h>
#include <math.h>
#include <stdint.h>

#define BSZ 32
#define SEQ 2048
#define DIM 512
#define DGLU 1024
#define MROWS (BSZ * SEQ)
#define SCAN_TS 32
#define SCAN_CH (SEQ / SCAN_TS)

#define SROW 20             // padded floats per smem row (16 + 4)
#define TILEF (128 * SROW)  // floats per matrix tile
#define STAGEF (2 * TILEF)  // A + B per stage
#define NSTAGE 4
#define SMEM_BYTES (NSTAGE * STAGEF * 4)   // 81920

__device__ float g_bufA[(size_t)MROWS * DIM];
__device__ float g_bufB[(size_t)MROWS * DIM];
__device__ float g_bufC[(size_t)MROWS * DIM];
__device__ float g_bufD[(size_t)MROWS * DIM];
__device__ float g_bufE[(size_t)MROWS * DGLU];
__device__ float g_bufF[(size_t)MROWS * DGLU];
__device__ float g_WT[2621440];

__device__ __forceinline__ float sigmoidf_(float v) { return 1.f / (1.f + expf(-v)); }
__device__ __forceinline__ float rnd32(float f) {
    uint32_t u; asm("cvt.rna.tf32.f32 %0, %1;" : "=r"(u) : "f"(f));
    return __uint_as_float(u);
}

enum { MODE_PLAIN = 0, MODE_SIG = 1, MODE_LAM = 2, MODE_U = 3, MODE_GLU = 4 };

__device__ __forceinline__ void mma_tf32(float* d, const uint32_t* a, const uint32_t* b) {
    asm volatile("mma.sync.aligned.m16n8k8.row.col.f32.tf32.tf32.f32 "
                 "{%0,%1,%2,%3}, {%4,%5,%6,%7}, {%8,%9}, {%0,%1,%2,%3};"
                 : "+f"(d[0]), "+f"(d[1]), "+f"(d[2]), "+f"(d[3])
                 : "r"(a[0]), "r"(a[1]), "r"(a[2]), "r"(a[3]), "r"(b[0]), "r"(b[1]));
}
__device__ __forceinline__ void cpasync16(uint32_t dst, const void* src) {
    asm volatile("cp.async.cg.shared.global [%0], [%1], 16;" :: "r"(dst), "l"(src));
}
__device__ __forceinline__ uint32_t smem_u32(const void* p) {
    uint32_t a;
    asm("{ .reg .u64 t; cvta.to.shared.u64 t, %1; cvt.u32.u64 %0, t; }" : "=r"(a) : "l"(p));
    return a;
}

// issue cp.async for one 128x16 A tile + 128x16 B tile (inputs pre-rounded to tf32)
__device__ __forceinline__ void stage_in(uint32_t smem_stage_u, const float* Ab, const float* Bb,
                                         int K, int kc, int tid) {
#pragma unroll
    for (int i = 0; i < 4; i++) {
        const int idx = tid + i * 256;          // 0..1023
        const int mat = idx >> 9;               // 0=A, 1=B
        const int r   = (idx >> 2) & 127;
        const int c4  = idx & 3;
        const float* src = (mat ? Bb : Ab) + (size_t)r * K + kc * 16 + c4 * 4;
        const uint32_t dst = smem_stage_u + (uint32_t)(mat * TILEF + r * SROW + c4 * 4) * 4u;
        cpasync16(dst, src);
    }
}

// C[M,N] = epilogue(A[M,K] @ WT[N,K]^T + bias); A, WT pre-rounded to tf32 bits
template <int MODE, bool ROUND>
__global__ __launch_bounds__(256)
void tc_gemm(const float* __restrict__ A, const float* __restrict__ WT,
             const float* __restrict__ bias, float* __restrict__ C,
             const float* __restrict__ aux, const float* __restrict__ lbp, int N, int K)
{
    extern __shared__ float sm[];

    const int tid = threadIdx.x, wid = tid >> 5, lane = tid & 31;
    const int g = lane >> 2, cc = lane & 3;
    const int bm = blockIdx.y * 128, bn = blockIdx.x * 128;
    const int wm = (wid >> 2) * 64, wn = (wid & 3) * 32;
    const uint32_t sm_u = smem_u32(sm);

    const float* Ab = A + (size_t)bm * K;
    const float* Bb = WT + (size_t)bn * K;
    const int NK = K >> 4;

    float acc[4][4][4];
#pragma unroll
    for (int mf = 0; mf < 4; mf++)
#pragma unroll
        for (int nf = 0; nf < 4; nf++)
#pragma unroll
            for (int k = 0; k < 4; k++) acc[mf][nf][k] = 0.f;

    // prologue: 3 stages in flight
#pragma unroll
    for (int s = 0; s < 3; s++) {
        stage_in(sm_u + s * STAGEF * 4, Ab, Bb, K, s, tid);
        asm volatile("cp.async.commit_group;");
    }

    for (int kc = 0; kc < NK; kc++) {
        asm volatile("cp.async.wait_group 2;");
        __syncthreads();
        if (kc + 3 < NK)
            stage_in(sm_u + ((kc + 3) & 3) * STAGEF * 4, Ab, Bb, K, kc + 3, tid);
        asm volatile("cp.async.commit_group;");

        const float* As = sm + (kc & 3) * STAGEF;
        const float* Bs = As + TILEF;
#pragma unroll
        for (int ks = 0; ks < 2; ks++) {
            uint32_t af[4][4], bf[4][2];
#pragma unroll
            for (int mf = 0; mf < 4; mf++) {
                const float* p = As + (wm + mf * 16 + g) * SROW + ks * 8 + cc;
                af[mf][0] = __float_as_uint(p[0]);
                af[mf][1] = __float_as_uint(p[8 * SROW]);
                af[mf][2] = __float_as_uint(p[4]);
                af[mf][3] = __float_as_uint(p[8 * SROW + 4]);
            }
#pragma unroll
            for (int nf = 0; nf < 4; nf++) {
                const float* q = Bs + (wn + nf * 8 + g) * SROW + ks * 8 + cc;
                bf[nf][0] = __float_as_uint(q[0]);
                bf[nf][1] = __float_as_uint(q[4]);
            }
#pragma unroll
            for (int mf = 0; mf < 4; mf++)
#pragma unroll
                for (int nf = 0; nf < 4; nf++)
                    mma_tf32(acc[mf][nf], af[mf], bf[nf]);
        }
        __syncthreads();
    }

    float lb = 0.f;
    if (MODE == MODE_LAM) lb = __ldg(lbp);

#pragma unroll
    for (int mf = 0; mf < 4; mf++) {
#pragma unroll
        for (int half = 0; half < 2; half++) {
            const int row = bm + wm + mf * 16 + g + half * 8;
            float* Crow = C + (size_t)row * N;
            const float* Arow = (MODE == MODE_U || MODE == MODE_GLU)
                                ? aux + (size_t)row * N : nullptr;
#pragma unroll
            for (int nf = 0; nf < 4; nf++) {
                const int col = bn + wn + nf * 8 + cc * 2;
                const float2 bb = *(const float2*)&bias[col];
                float v0 = acc[mf][nf][half * 2 + 0] + bb.x;
                float v1 = acc[mf][nf][half * 2 + 1] + bb.y;
                float o0, o1;
                if (MODE == MODE_PLAIN) {
                    o0 = v0; o1 = v1;
                } else if (MODE == MODE_SIG) {
                    o0 = sigmoidf_(v0); o1 = sigmoidf_(v1);
                } else if (MODE == MODE_LAM) {
                    o0 = lb + (1.f - lb) * sigmoidf_(v0);
                    o1 = lb + (1.f - lb) * sigmoidf_(v1);
                } else if (MODE == MODE_U) {
                    const float2 ax = *(const float2*)(Arow + col);
                    o0 = (1.f - ax.x) * (v0 * sigmoidf_(v0));
                    o1 = (1.f - ax.y) * (v1 * sigmoidf_(v1));
                } else {
                    const float2 ax = *(const float2*)(Arow + col);
                    o0 = (v0 * sigmoidf_(v0)) * ax.x;
                    o1 = (v1 * sigmoidf_(v1)) * ax.y;
                }
                if (ROUND) { o0 = rnd32(o0); o1 = rnd32(o1); }
                float2 o; o.x = o0; o.y = o1;
                *(float2*)(Crow + col) = o;
            }
        }
    }
}

// dst[n*K+k] = round_tf32(src[k*N+n])
__global__ void transpose_w(const float* __restrict__ src, float* __restrict__ dst, int K, int N) {
    __shared__ float tile[32][33];
    const int n0 = blockIdx.x * 32, k0 = blockIdx.y * 32;
    for (int i = threadIdx.y; i < 32; i += 8)
        tile[i][threadIdx.x] = src[(size_t)(k0 + i) * N + n0 + threadIdx.x];
    __syncthreads();
    for (int i = threadIdx.y; i < 32; i += 8)
        dst[(size_t)(n0 + i) * K + k0 + threadIdx.x] = rnd32(tile[threadIdx.x][i]);
}

__global__ void round_x(const float* __restrict__ src, float* __restrict__ dst) {
    const size_t i = (size_t)blockIdx.x * blockDim.x + threadIdx.x;
    float4 v = *(const float4*)(src + i * 4);
    v.x = rnd32(v.x); v.y = rnd32(v.y); v.z = rnd32(v.z); v.w = rnd32(v.w);
    *(float4*)(dst + i * 4) = v;
}

__global__ __launch_bounds__(512)
void scan_pass1(const float* __restrict__ lam, const float* __restrict__ u,
                float* __restrict__ lF, float* __restrict__ lB,
                float* __restrict__ prod, float* __restrict__ lastF, float* __restrict__ lastB)
{
    const int b = blockIdx.x >> 6, ch = blockIdx.x & 63;
    const int d = threadIdx.x;
    const size_t base = ((size_t)b * SEQ + ch * SCAN_TS) * DIM + d;
    float hf = 0.f, p = 1.f;
#pragma unroll 4
    for (int t = 0; t < SCAN_TS; t++) {
        const size_t ix = base + (size_t)t * DIM;
        const float l = lam[ix];
        hf = fmaf(l, hf, u[ix]); p *= l; lF[ix] = hf;
    }
    float hb = 0.f;
#pragma unroll 4
    for (int t = SCAN_TS - 1; t >= 0; t--) {
        const size_t ix = base + (size_t)t * DIM;
        hb = fmaf(lam[ix], hb, u[ix]); lB[ix] = hb;
    }
    const int ci = (b * SCAN_CH + ch) * DIM + d;
    prod[ci] = p; lastF[ci] = hf; lastB[ci] = hb;
}

__global__ void scan_pass2(const float* __restrict__ prod, const float* __restrict__ lastF,
                           const float* __restrict__ lastB, float* __restrict__ CF, float* __restrict__ CB)
{
    const int c = blockIdx.x * blockDim.x + threadIdx.x;
    if (c >= BSZ * DIM) return;
    const int b = c >> 9, d = c & 511;
    float cf = 0.f;
    for (int ch = 0; ch < SCAN_CH; ch++) {
        const int i = (b * SCAN_CH + ch) * DIM + d;
        CF[i] = cf; cf = fmaf(prod[i], cf, lastF[i]);
    }
    float cb = 0.f;
    for (int ch = SCAN_CH - 1; ch >= 0; ch--) {
        const int i = (b * SCAN_CH + ch) * DIM + d;
        CB[i] = cb; cb = fmaf(prod[i], cb, lastB[i]);
    }
}

__global__ __launch_bounds__(512)
void scan_pass3(const float* __restrict__ lam, const float* __restrict__ lF,
                const float* __restrict__ lB, const float* __restrict__ CF,
                const float* __restrict__ CB, float* __restrict__ h)
{
    const int b = blockIdx.x >> 6, ch = blockIdx.x & 63;
    const int d = threadIdx.x;
    const size_t base = ((size_t)b * SEQ + ch * SCAN_TS) * DIM + d;
    const int ci = (b * SCAN_CH + ch) * DIM + d;
    const float cf = CF[ci], cb = CB[ci];
    float vals[SCAN_TS];
    float p = 1.f;
#pragma unroll
    for (int t = 0; t < SCAN_TS; t++) {
        const size_t ix = base + (size_t)t * DIM;
        p *= lam[ix];
        vals[t] = fmaf(cf, p, lF[ix]);
    }
    float q = 1.f;
#pragma unroll
    for (int t = SCAN_TS - 1; t >= 0; t--) {
        const size_t ix = base + (size_t)t * DIM;
        q *= lam[ix];
        h[ix] = vals[t] + fmaf(cb, q, lB[ix]);
    }
}

// out = round_tf32(rmsnorm(h) * g)   (output feeds a GEMM only)
__global__ void rms_gate(const float* __restrict__ h, const float* __restrict__ g, float* __restrict__ out) {
    const int row = blockIdx.x * 8 + (threadIdx.x >> 5), lane = threadIdx.x & 31;
    const float* hr = h + (size_t)row * DIM;
    float4 v[4]; float ss = 0.f;
#pragma unroll
    for (int i = 0; i < 4; i++) {
        v[i] = *(const float4*)(hr + i * 128 + lane * 4);
        ss += v[i].x * v[i].x + v[i].y * v[i].y + v[i].z * v[i].z + v[i].w * v[i].w;
    }
#pragma unroll
    for (int o = 16; o > 0; o >>= 1) ss += __shfl_xor_sync(0xffffffffu, ss, o);
    const float sc = rsqrtf(ss * (1.f / DIM) + 1e-6f);
    const float* gr = g + (size_t)row * DIM;
    float* outr = out + (size_t)row * DIM;
#pragma unroll
    for (int i = 0; i < 4; i++) {
        float4 gv = *(const float4*)(gr + i * 128 + lane * 4);
        float4 r;
        r.x = rnd32(v[i].x * sc * gv.x); r.y = rnd32(v[i].y * sc * gv.y);
        r.z = rnd32(v[i].z * sc * gv.z); r.w = rnd32(v[i].w * sc * gv.w);
        *(float4*)(outr + i * 128 + lane * 4) = r;
    }
}

// out = resid + LN(y)*gam + bet ; optional rounded copy (for downstream GEMM)
__global__ void ln_add(const float* __restrict__ y, const float* __restrict__ resid,
                       const float* __restrict__ gam, const float* __restrict__ bet,
                       float* __restrict__ out, float* __restrict__ outR) {
    const int row = blockIdx.x * 8 + (threadIdx.x >> 5), lane = threadIdx.x & 31;
    const float* yr = y + (size_t)row * DIM;
    float4 v[4]; float s1 = 0.f, s2 = 0.f;
#pragma unroll
    for (int i = 0; i < 4; i++) {
        v[i] = *(const float4*)(yr + i * 128 + lane * 4);
        s1 += v[i].x + v[i].y + v[i].z + v[i].w;
        s2 += v[i].x * v[i].x + v[i].y * v[i].y + v[i].z * v[i].z + v[i].w * v[i].w;
    }
#pragma unroll
    for (int o = 16; o > 0; o >>= 1) {
        s1 += __shfl_xor_sync(0xffffffffu, s1, o);
        s2 += __shfl_xor_sync(0xffffffffu, s2, o);
    }
    const float mean = s1 * (1.f / DIM);
    const float inv = rsqrtf(s2 * (1.f / DIM) - mean * mean + 1e-5f);
    const float* rr = resid + (size_t)row * DIM;
    float* outr = out + (size_t)row * DIM;
    float* outr2 = outR ? outR + (size_t)row * DIM : nullptr;
#pragma unroll
    for (int i = 0; i < 4; i++) {
        const int col = i * 128 + lane * 4;
        float4 gv = *(const float4*)(gam + col);
        float4 bv = *(const float4*)(bet + col);
        float4 xv = *(const float4*)(rr + col);
        float4 r;
        r.x = xv.x + (v[i].x - mean) * inv * gv.x + bv.x;
        r.y = xv.y + (v[i].y - mean) * inv * gv.y + bv.y;
        r.z = xv.z + (v[i].z - mean) * inv * gv.z + bv.z;
        r.w = xv.w + (v[i].w - mean) * inv * gv.w + bv.w;
        *(float4*)(outr + col) = r;
        if (outr2) {
            float4 r2;
            r2.x = rnd32(r.x); r2.y = rnd32(r.y); r2.z = rnd32(r.z); r2.w = rnd32(r.w);
            *(float4*)(outr2 + col) = r2;
        }
    }
}

extern "C" void kernel_launch(void* const* d_in, const int* in_sizes, int n_in,
                              void* d_out, int out_size)
{
    const float* x = (const float*)d_in[0];
    const float* lbp = (const float*)d_in[1];
    const float* Wi = (const float*)d_in[2];  const float* bi = (const float*)d_in[3];
    const float* Wf = (const float*)d_in[4];  const float* bf = (const float*)d_in[5];
    const float* Wg = (const float*)d_in[6];  const float* bg = (const float*)d_in[7];
    const float* Wo = (const float*)d_in[8];  const float* bo = (const float*)d_in[9];
    const float* tn_g = (const float*)d_in[10]; const float* tn_b = (const float*)d_in[11];
    const float* fn_g = (const float*)d_in[12]; const float* fn_b = (const float*)d_in[13];
    const float* W1 = (const float*)d_in[14]; const float* b1 = (const float*)d_in[15];
    const float* W2 = (const float*)d_in[16]; const float* b2 = (const float*)d_in[17];
    const float* W3 = (const float*)d_in[18]; const float* b3 = (const float*)d_in[19];
    float* out = (float*)d_out;

    float *bA, *bB, *bC, *bD, *bE, *bF, *wt;
    cudaGetSymbolAddress((void**)&bA, g_bufA);
    cudaGetSymbolAddress((void**)&bB, g_bufB);
    cudaGetSymbolAddress((void**)&bC, g_bufC);
    cudaGetSymbolAddress((void**)&bD, g_bufD);
    cudaGetSymbolAddress((void**)&bE, g_bufE);
    cudaGetSymbolAddress((void**)&bF, g_bufF);
    cudaGetSymbolAddress((void**)&wt, g_WT);

    float* WiT = wt;
    float* WfT = wt + 262144;
    float* WgT = wt + 524288;
    float* WoT = wt + 786432;
    float* W1T = wt + 1048576;
    float* W2T = wt + 1572864;
    float* W3T = wt + 2097152;

    float* lF = bE;
    float* lB = bF;
    float* prod  = bE + (size_t)MROWS * DIM;
    float* lastF = prod + (size_t)BSZ * SCAN_CH * DIM;
    float* lastB = lastF + (size_t)BSZ * SCAN_CH * DIM;
    float* CF = bF + (size_t)MROWS * DIM;
    float* CB = CF + (size_t)BSZ * SCAN_CH * DIM;

    // raise dynamic smem limits (idempotent)
    cudaFuncSetAttribute(tc_gemm<MODE_PLAIN, false>, cudaFuncAttributeMaxDynamicSharedMemorySize, SMEM_BYTES);
    cudaFuncSetAttribute(tc_gemm<MODE_SIG,   false>, cudaFuncAttributeMaxDynamicSharedMemorySize, SMEM_BYTES);
    cudaFuncSetAttribute(tc_gemm<MODE_LAM,   false>, cudaFuncAttributeMaxDynamicSharedMemorySize, SMEM_BYTES);
    cudaFuncSetAttribute(tc_gemm<MODE_U,     false>, cudaFuncAttributeMaxDynamicSharedMemorySize, SMEM_BYTES);
    cudaFuncSetAttribute(tc_gemm<MODE_GLU,   true>,  cudaFuncAttributeMaxDynamicSharedMemorySize, SMEM_BYTES);

    dim3 tb(32, 8);
    round_x<<<32768, 256>>>(x, bD);    // xr = tf32(x)
    transpose_w<<<dim3(16, 16), tb>>>(Wi, WiT, DIM, DIM);
    transpose_w<<<dim3(16, 16), tb>>>(Wf, WfT, DIM, DIM);
    transpose_w<<<dim3(16, 16), tb>>>(Wg, WgT, DIM, DIM);
    transpose_w<<<dim3(16, 16), tb>>>(Wo, WoT, DIM, DIM);
    transpose_w<<<dim3(32, 16), tb>>>(W1, W1T, DIM, DGLU);
    transpose_w<<<dim3(32, 16), tb>>>(W2, W2T, DIM, DGLU);
    transpose_w<<<dim3(16, 32), tb>>>(W3, W3T, DGLU, DIM);

    dim3 blk(256);
    dim3 gD(DIM / 128, MROWS / 128);
    dim3 gG(DGLU / 128, MROWS / 128);
    const int rowsBlocks = MROWS / 8;
    const int scanBlocks = BSZ * SCAN_CH;

    tc_gemm<MODE_LAM, false><<<gD, blk, SMEM_BYTES>>>(bD, WfT, bf, bA, nullptr, lbp, DIM, DIM);
    tc_gemm<MODE_U,   false><<<gD, blk, SMEM_BYTES>>>(bD, WiT, bi, bB, bA, nullptr, DIM, DIM);
    tc_gemm<MODE_SIG, false><<<gD, blk, SMEM_BYTES>>>(bD, WgT, bg, bC, nullptr, nullptr, DIM, DIM);
    scan_pass1<<<scanBlocks, DIM>>>(bA, bB, lF, lB, prod, lastF, lastB);
    scan_pass2<<<(BSZ * DIM + 255) / 256, 256>>>(prod, lastF, lastB, CF, CB);
    scan_pass3<<<scanBlocks, DIM>>>(bA, lF, lB, CF, CB, bD);
    rms_gate<<<rowsBlocks, 256>>>(bD, bC, bA);
    tc_gemm<MODE_PLAIN, false><<<gD, blk, SMEM_BYTES>>>(bA, WoT, bo, bB, nullptr, nullptr, DIM, DIM);
    ln_add<<<rowsBlocks, 256>>>(bB, x, tn_g, tn_b, bC, bD);   // bC = x1 (full), bD = tf32(x1)
    tc_gemm<MODE_PLAIN, false><<<gG, blk, SMEM_BYTES>>>(bD, W2T, b2, bE, nullptr, nullptr, DGLU, DIM);
    tc_gemm<MODE_GLU,  true><<<gG, blk, SMEM_BYTES>>>(bD, W1T, b1, bF, bE, nullptr, DGLU, DIM);
    tc_gemm<MODE_PLAIN, false><<<gD, blk, SMEM_BYTES>>>(bF, W3T, b3, bA, nullptr, nullptr, DIM, DGLU);
    ln_add<<<rowsBlocks, 256>>>(bA, bC, fn_g, fn_b, out, nullptr);
}